// round 2
// baseline (speedup 1.0000x reference)
#include <cuda_runtime.h>

#define BB 2
#define SS 2048
#define HH 1024
#define NH 16
#define HD 64
#define ND 4095   // 2*MAX_POS - 1

// Scratch for q, k, v in [b*NH+h][s][d] layout (16 MB each)
__device__ float g_q[BB * NH * SS * HD];
__device__ float g_k[BB * NH * SS * HD];
__device__ float g_v[BB * NH * SS * HD];

// ---------------------------------------------------------------------------
// Kernel 1: fused QKV projection.  C[4096,3072] = A[4096,1024] @ W[1024,3072]
// + bias, scattered into g_q/g_k/g_v with [b,h,s,d] layout.
// 128x128 block tile, 8x8 per thread, K-tile 8.
// ---------------------------------------------------------------------------
__global__ __launch_bounds__(256) void qkv_kernel(
    const float* __restrict__ A, const float* __restrict__ W,
    const float* __restrict__ bias)
{
    __shared__ float As[8][128];
    __shared__ float Ws[8][128];
    const int tid = threadIdx.x;
    const int bx = blockIdx.x, by = blockIdx.y;
    const int tx = tid % 16, ty = tid / 16;

    float acc[8][8];
#pragma unroll
    for (int i = 0; i < 8; i++)
#pragma unroll
        for (int j = 0; j < 8; j++) acc[i][j] = 0.f;

    const int ar = tid >> 1;            // 0..127
    const int ac = (tid & 1) * 4;       // 0 or 4
    const int wr = tid >> 5;            // 0..7
    const int wc = (tid & 31) * 4;      // 0..124

    const float* Aptr = A + (size_t)(by * 128 + ar) * HH + ac;
    const float* Wptr = W + (size_t)wr * 3072 + bx * 128 + wc;

    for (int kt = 0; kt < HH / 8; kt++) {
        float4 av = *(const float4*)(Aptr + kt * 8);
        float4 wv = *(const float4*)(Wptr + (size_t)kt * 8 * 3072);
        As[ac + 0][ar] = av.x; As[ac + 1][ar] = av.y;
        As[ac + 2][ar] = av.z; As[ac + 3][ar] = av.w;
        *(float4*)&Ws[wr][wc] = wv;
        __syncthreads();
#pragma unroll
        for (int k = 0; k < 8; k++) {
            float a[8], b[8];
#pragma unroll
            for (int i = 0; i < 8; i++) a[i] = As[k][ty * 8 + i];
#pragma unroll
            for (int j = 0; j < 8; j++) b[j] = Ws[k][tx * 8 + j];
#pragma unroll
            for (int i = 0; i < 8; i++)
#pragma unroll
                for (int j = 0; j < 8; j++) acc[i][j] += a[i] * b[j];
        }
        __syncthreads();
    }

    // Scatter: col n -> (which, h, d).  tx*8 octet never crosses a 64 boundary.
    const int n0 = bx * 128 + tx * 8;
    const int which = n0 / 1024;
    const int h = (n0 % 1024) / 64;
    const int d0 = n0 % 64;
    float* dst = (which == 0) ? g_q : (which == 1) ? g_k : g_v;
    float bv[8];
#pragma unroll
    for (int j = 0; j < 8; j++) bv[j] = bias[n0 + j];

#pragma unroll
    for (int i = 0; i < 8; i++) {
        int m = by * 128 + ty * 8 + i;
        int b = m / SS, s = m % SS;
        float* p = dst + ((size_t)(b * NH + h) * SS + s) * HD + d0;
        float4 o0 = make_float4(acc[i][0] + bv[0], acc[i][1] + bv[1],
                                acc[i][2] + bv[2], acc[i][3] + bv[3]);
        float4 o1 = make_float4(acc[i][4] + bv[4], acc[i][5] + bv[5],
                                acc[i][6] + bv[6], acc[i][7] + bv[7]);
        *(float4*)p = o0;
        *(float4*)(p + 4) = o1;
    }
}

// ---------------------------------------------------------------------------
// Kernel 2: scores[l,r] = inv_scale * q.k + (q + k) . E[l-r+2047] + mask[r]
// 64x64 tile per block; Toeplitz structure -> only 127 E rows per tile.
// smem layouts are d-major with padding to kill bank conflicts.
// Dynamic smem: qs[64][65] + ks[64][65] + es[64][129] = 66304 bytes.
// ---------------------------------------------------------------------------
__global__ __launch_bounds__(256) void score_kernel(
    const float* __restrict__ dist_emb, const float* __restrict__ mask,
    float* __restrict__ probs)
{
    extern __shared__ float sm[];
    float* qs = sm;                 // qs[d*65 + u]
    float* ks = sm + 64 * 65;       // ks[d*65 + v]
    float* es = sm + 2 * 64 * 65;   // es[d*129 + j], j in [0,126]

    const int tid = threadIdx.x;
    const int rt = blockIdx.x, lt = blockIdx.y, z = blockIdx.z;
    const int l0 = lt * 64, r0 = rt * 64;

    const float* qg = g_q + ((size_t)z * SS + l0) * HD;
    const float* kg = g_k + ((size_t)z * SS + r0) * HD;

    const int lr = tid / 16;            // 0..15
    const int d4 = (tid % 16) * 4;      // 0..60

#pragma unroll
    for (int g = 0; g < 4; g++) {
        int u = lr + 16 * g;
        float4 qv = *(const float4*)(qg + (size_t)u * HD + d4);
        qs[(d4 + 0) * 65 + u] = qv.x; qs[(d4 + 1) * 65 + u] = qv.y;
        qs[(d4 + 2) * 65 + u] = qv.z; qs[(d4 + 3) * 65 + u] = qv.w;
        float4 kv = *(const float4*)(kg + (size_t)u * HD + d4);
        ks[(d4 + 0) * 65 + u] = kv.x; ks[(d4 + 1) * 65 + u] = kv.y;
        ks[(d4 + 2) * 65 + u] = kv.z; ks[(d4 + 3) * 65 + u] = kv.w;
    }

    const int base_dist = l0 - r0 + 1984;  // dist for j=0; in [0, 3968]
#pragma unroll
    for (int g = 0; g < 8; g++) {
        int j = lr + 16 * g;
        if (j < 127) {
            float4 ev = *(const float4*)(dist_emb + (size_t)(base_dist + j) * HD + d4);
            es[(d4 + 0) * 129 + j] = ev.x; es[(d4 + 1) * 129 + j] = ev.y;
            es[(d4 + 2) * 129 + j] = ev.z; es[(d4 + 3) * 129 + j] = ev.w;
        }
    }
    __syncthreads();

    const int tx = tid % 16, ty = tid / 16;
    const int u0 = ty * 4, v0 = tx * 4;
    const int j0 = u0 - v0 + 60;   // j for (iu-iv) = -3

    float aqk[4][4], ae[4][4];
#pragma unroll
    for (int i = 0; i < 4; i++)
#pragma unroll
        for (int j = 0; j < 4; j++) { aqk[i][j] = 0.f; ae[i][j] = 0.f; }

#pragma unroll 4
    for (int d = 0; d < 64; d++) {
        float qv[4], kv[4], ev[7];
#pragma unroll
        for (int i = 0; i < 4; i++) qv[i] = qs[d * 65 + u0 + i];
#pragma unroll
        for (int i = 0; i < 4; i++) kv[i] = ks[d * 65 + v0 + i];
#pragma unroll
        for (int t = 0; t < 7; t++) ev[t] = es[d * 129 + j0 + t];
#pragma unroll
        for (int iu = 0; iu < 4; iu++)
#pragma unroll
            for (int iv = 0; iv < 4; iv++) {
                aqk[iu][iv] += qv[iu] * kv[iv];
                ae[iu][iv] += (qv[iu] + kv[iv]) * ev[iu - iv + 3];
            }
    }

    const float inv_scale = 0.125f;
    const int b = z / NH;
    float mk[4];
#pragma unroll
    for (int iv = 0; iv < 4; iv++) mk[iv] = mask[b * SS + r0 + v0 + iv];

    float* out = probs + ((size_t)z * SS + l0 + u0) * SS + r0 + v0;
#pragma unroll
    for (int iu = 0; iu < 4; iu++) {
        float4 o;
        o.x = aqk[iu][0] * inv_scale + ae[iu][0] + mk[0];
        o.y = aqk[iu][1] * inv_scale + ae[iu][1] + mk[1];
        o.z = aqk[iu][2] * inv_scale + ae[iu][2] + mk[2];
        o.w = aqk[iu][3] * inv_scale + ae[iu][3] + mk[3];
        *(float4*)(out + (size_t)iu * SS) = o;
    }
}

// ---------------------------------------------------------------------------
// Kernel 3: in-place row softmax over 2048 elements. One 256-thread block per row.
// ---------------------------------------------------------------------------
__global__ __launch_bounds__(256) void softmax_kernel(float* __restrict__ probs)
{
    __shared__ float red[256];
    const int tid = threadIdx.x;
    float4* p = (float4*)(probs + (size_t)blockIdx.x * SS);

    float4 x0 = p[tid];
    float4 x1 = p[tid + 256];

    float m = fmaxf(fmaxf(fmaxf(x0.x, x0.y), fmaxf(x0.z, x0.w)),
                    fmaxf(fmaxf(x1.x, x1.y), fmaxf(x1.z, x1.w)));
    red[tid] = m;
    __syncthreads();
#pragma unroll
    for (int s = 128; s > 0; s >>= 1) {
        if (tid < s) red[tid] = fmaxf(red[tid], red[tid + s]);
        __syncthreads();
    }
    m = red[0];
    __syncthreads();

    x0.x = __expf(x0.x - m); x0.y = __expf(x0.y - m);
    x0.z = __expf(x0.z - m); x0.w = __expf(x0.w - m);
    x1.x = __expf(x1.x - m); x1.y = __expf(x1.y - m);
    x1.z = __expf(x1.z - m); x1.w = __expf(x1.w - m);

    float sum = (x0.x + x0.y) + (x0.z + x0.w) + (x1.x + x1.y) + (x1.z + x1.w);
    red[tid] = sum;
    __syncthreads();
#pragma unroll
    for (int s = 128; s > 0; s >>= 1) {
        if (tid < s) red[tid] += red[tid + s];
        __syncthreads();
    }
    float inv = 1.f / red[0];

    x0.x *= inv; x0.y *= inv; x0.z *= inv; x0.w *= inv;
    x1.x *= inv; x1.y *= inv; x1.z *= inv; x1.w *= inv;
    p[tid] = x0;
    p[tid + 256] = x1;
}

// ---------------------------------------------------------------------------
// Kernel 4: ctx = probs @ v.   Per (z, l-tile of 128): out [128 l x 64 d].
// r staged in 32-wide tiles. Thread computes 8(l) x 4(d).
// ---------------------------------------------------------------------------
__global__ __launch_bounds__(256) void pv_kernel(
    const float* __restrict__ probs, float* __restrict__ ctx)
{
    __shared__ float ps[32 * 132];  // [r][l], padded stride 132
    __shared__ float vs[32 * 68];   // [r][d], padded stride 68

    const int z = blockIdx.y;
    const int l0 = blockIdx.x * 128;
    const int tid = threadIdx.x;
    const int tx = tid % 16, ty = tid / 16;

    float acc[8][4];
#pragma unroll
    for (int i = 0; i < 8; i++)
#pragma unroll
        for (int j = 0; j < 4; j++) acc[i][j] = 0.f;

    const float* pg = probs + ((size_t)z * SS + l0) * SS;
    const float* vg = g_v + (size_t)z * SS * HD;

    const int pl = tid / 8;          // 0..31
    const int pr4 = (tid % 8) * 4;   // 0..28
    const int vr = tid / 16;         // 0..15
    const int vd4 = (tid % 16) * 4;  // 0..60

    for (int rt = 0; rt < 64; rt++) {
#pragma unroll
        for (int g = 0; g < 4; g++) {
            int l = pl + 32 * g;
            float4 pv = *(const float4*)(pg + (size_t)l * SS + rt * 32 + pr4);
            ps[(pr4 + 0) * 132 + l] = pv.x; ps[(pr4 + 1) * 132 + l] = pv.y;
            ps[(pr4 + 2) * 132 + l] = pv.z; ps[(pr4 + 3) * 132 + l] = pv.w;
        }
#pragma unroll
        for (int g = 0; g < 2; g++) {
            int r = vr + 16 * g;
            float4 vv = *(const float4*)(vg + (size_t)(rt * 32 + r) * HD + vd4);
            *(float4*)&vs[r * 68 + vd4] = vv;
        }
        __syncthreads();
#pragma unroll
        for (int r = 0; r < 32; r++) {
            float a[8], b[4];
#pragma unroll
            for (int i = 0; i < 8; i++) a[i] = ps[r * 132 + ty * 8 + i];
#pragma unroll
            for (int j = 0; j < 4; j++) b[j] = vs[r * 68 + tx * 4 + j];
#pragma unroll
            for (int i = 0; i < 8; i++)
#pragma unroll
                for (int j = 0; j < 4; j++) acc[i][j] += a[i] * b[j];
        }
        __syncthreads();
    }

    const int b = z / NH, h = z % NH;
#pragma unroll
    for (int i = 0; i < 8; i++) {
        int l = l0 + ty * 8 + i;
        float* o = ctx + ((size_t)b * SS + l) * HH + h * HD + tx * 4;
        *(float4*)o = make_float4(acc[i][0], acc[i][1], acc[i][2], acc[i][3]);
    }
}

// ---------------------------------------------------------------------------
extern "C" void kernel_launch(void* const* d_in, const int* in_sizes, int n_in,
                              void* d_out, int out_size)
{
    const float* hidden   = (const float*)d_in[0];  // [2,2048,1024]
    const float* mask     = (const float*)d_in[1];  // [2,1,1,2048]
    const float* qkv_w    = (const float*)d_in[2];  // [1024,3072]
    const float* qkv_b    = (const float*)d_in[3];  // [3072]
    const float* dist_emb = (const float*)d_in[4];  // [4095,64]

    float* out = (float*)d_out;
    float* ctx = out;                                   // [2,2048,1024]
    float* probs = out + (size_t)BB * SS * HH;          // [2,16,2048,2048]

    // 1) QKV projection -> g_q/g_k/g_v
    qkv_kernel<<<dim3(3072 / 128, 4096 / 128), 256>>>(hidden, qkv_w, qkv_b);

    // 2) scores (+ relative position bias + mask) -> probs buffer (raw)
    const int score_smem = (2 * 64 * 65 + 64 * 129) * 4;  // 66304 B
    cudaFuncSetAttribute(score_kernel,
                         cudaFuncAttributeMaxDynamicSharedMemorySize, score_smem);
    score_kernel<<<dim3(SS / 64, SS / 64, BB * NH), 256, score_smem>>>(
        dist_emb, mask, probs);

    // 3) softmax in place
    softmax_kernel<<<BB * NH * SS, 256>>>(probs);

    // 4) ctx = probs @ v
    pv_kernel<<<dim3(SS / 128, BB * NH), 256>>>(probs, ctx);
}